// round 1
// baseline (speedup 1.0000x reference)
#include <cuda_runtime.h>
#include <math.h>

#define HC   128
#define NH   8
#define COLS 256
#define MAXN 50000
#define MAXM 400000

// Scratch (device globals — no allocation allowed)
__device__ float g_q[MAXN * HC];
__device__ float g_k[MAXN * HC];
__device__ float g_v[MAXN * HC];
__device__ float g_agg[MAXN * HC];
__device__ float g_segmax[MAXN * NH];
__device__ float g_denom[MAXN * NH];
__device__ float g_ex[MAXM * NH];

__device__ __forceinline__ void atomicMaxFloat(float* addr, float val) {
    if (val >= 0.0f) {
        atomicMax((int*)addr, __float_as_int(val));
    } else {
        atomicMin((unsigned int*)addr, __float_as_uint(val));
    }
}

// ---------------------------------------------------------------------------
// Init: zero agg & denom, segmax = -inf
// ---------------------------------------------------------------------------
__global__ void k_init(int n) {
    int i = blockIdx.x * blockDim.x + threadIdx.x;
    if (i < n * HC) g_agg[i] = 0.0f;
    if (i < n * NH) {
        g_denom[i] = 0.0f;
        ((unsigned int*)g_segmax)[i] = 0xFF800000u;  // -inf
    }
}

// ---------------------------------------------------------------------------
// Projections: q = query@Wq ; k,v = key@Wkv split. 8 nodes per 128-thread block.
// ---------------------------------------------------------------------------
__global__ __launch_bounds__(128) void k_proj(
    const float* __restrict__ query, const float* __restrict__ key,
    const float* __restrict__ Wq, const float* __restrict__ Wkv, int n)
{
    __shared__ float sq[8][HC];
    __shared__ float sk[8][HC];
    int t  = threadIdx.x;
    int nb = blockIdx.x * 8;
    int cnt = n - nb; if (cnt > 8) cnt = 8;

    for (int nn = 0; nn < cnt; nn++) {
        sq[nn][t] = query[(nb + nn) * HC + t];
        sk[nn][t] = key  [(nb + nn) * HC + t];
    }
    __syncthreads();

    float aq[8], ak[8], av[8];
#pragma unroll
    for (int nn = 0; nn < 8; nn++) { aq[nn] = 0.f; ak[nn] = 0.f; av[nn] = 0.f; }

#pragma unroll 4
    for (int kk = 0; kk < HC; kk++) {
        float wq = Wq [kk * HC   + t];
        float wk = Wkv[kk * COLS + t];
        float wv = Wkv[kk * COLS + HC + t];
#pragma unroll
        for (int nn = 0; nn < 8; nn++) {
            float pq = sq[nn][kk];
            float pk = sk[nn][kk];
            aq[nn] += pq * wq;
            ak[nn] += pk * wk;
            av[nn] += pk * wv;
        }
    }
    for (int nn = 0; nn < cnt; nn++) {
        g_q[(nb + nn) * HC + t] = aq[nn];
        g_k[(nb + nn) * HC + t] = ak[nn];
        g_v[(nb + nn) * HC + t] = av[nn];
    }
}

// ---------------------------------------------------------------------------
// Edge kernel: fused b = PR@Wb (M x 256, K=128) + bias-modulated logits +
// segment max. Wb resident in shared; 32-edge tiles; thread tile 4 edges x 8
// cols (cols = lane + 32j -> all same head = lane%8, conflict-free LDS).
// ---------------------------------------------------------------------------
__global__ __launch_bounds__(256) void k_edge(
    const float* __restrict__ paired, const float* __restrict__ Wb,
    const int* __restrict__ qidx, const int* __restrict__ kidx,
    float* __restrict__ out_logit, int m)
{
    extern __shared__ float smem[];
    float* s_wb = smem;               // [128][256]
    float* s_pr = smem + HC * COLS;   // [32][128]

    int tid  = threadIdx.x;
    int warp = tid >> 5;   // edge-group 0..7
    int lane = tid & 31;   // column base

    // Load Wb once per CTA
    for (int i = tid; i < HC * COLS; i += 256) s_wb[i] = Wb[i];

    int ntiles = (m + 31) >> 5;
    for (int tile = blockIdx.x; tile < ntiles; tile += gridDim.x) {
        int ebase = tile << 5;

        __syncthreads();  // previous-iter readers done (also covers Wb load on iter 0)
        for (int i = tid; i < 32 * HC; i += 256) {
            int e = ebase + (i >> 7);
            s_pr[i] = (e < m) ? paired[e * HC + (i & 127)] : 0.0f;
        }
        __syncthreads();

        float acc[4][8];
#pragma unroll
        for (int a = 0; a < 4; a++)
#pragma unroll
            for (int b = 0; b < 8; b++) acc[a][b] = 0.0f;

        const float* prw = s_pr + (warp << 2) * HC;

#pragma unroll 4
        for (int kk = 0; kk < HC; kk++) {
            float w[8];
#pragma unroll
            for (int j = 0; j < 8; j++) w[j] = s_wb[kk * COLS + lane + 32 * j];
            float p0 = prw[0 * HC + kk];
            float p1 = prw[1 * HC + kk];
            float p2 = prw[2 * HC + kk];
            float p3 = prw[3 * HC + kk];
#pragma unroll
            for (int j = 0; j < 8; j++) {
                acc[0][j] += p0 * w[j];
                acc[1][j] += p1 * w[j];
                acc[2][j] += p2 * w[j];
                acc[3][j] += p3 * w[j];
            }
        }

        // Epilogue: logit[e][h] = sum_c q[c]*(k[c]*(1+bm[c]) + ba[c]), h = c%8
#pragma unroll
        for (int a = 0; a < 4; a++) {
            int e = ebase + (warp << 2) + a;
            if (e < m) {  // uniform per warp
                int qi = qidx[e];
                int ki = kidx[e];
                float part = 0.0f;
#pragma unroll
                for (int j = 0; j < 4; j++) {
                    int c = lane + 32 * j;
                    float qv = __ldg(&g_q[qi * HC + c]);
                    float kv = __ldg(&g_k[ki * HC + c]);
                    part += qv * (kv * (1.0f + acc[a][j]) + acc[a][j + 4]);
                }
                part += __shfl_xor_sync(0xffffffffu, part, 8);
                part += __shfl_xor_sync(0xffffffffu, part, 16);
                if (lane < 8) {
                    out_logit[e * NH + lane] = part;
                    atomicMaxFloat(&g_segmax[qi * NH + lane], part);
                }
            }
        }
    }
}

// ---------------------------------------------------------------------------
// exp + denom accumulation
// ---------------------------------------------------------------------------
__global__ void k_exp(const int* __restrict__ qidx,
                      const float* __restrict__ logit, int m)
{
    int i = blockIdx.x * blockDim.x + threadIdx.x;
    if (i >= m * NH) return;
    int e = i >> 3, h = i & 7;
    int qi = qidx[e];
    float ex = expf(logit[i] - g_segmax[qi * NH + h]);
    g_ex[i] = ex;
    atomicAdd(&g_denom[qi * NH + h], ex);
}

// ---------------------------------------------------------------------------
// normalize: ex -> attn (in place)
// ---------------------------------------------------------------------------
__global__ void k_attn(const int* __restrict__ qidx, int m)
{
    int i = blockIdx.x * blockDim.x + threadIdx.x;
    if (i >= m * NH) return;
    int e = i >> 3, h = i & 7;
    g_ex[i] = g_ex[i] / g_denom[qidx[e] * NH + h];
}

// ---------------------------------------------------------------------------
// scatter: agg[qi] += attn * v[ki]
// ---------------------------------------------------------------------------
__global__ void k_scatter(const int* __restrict__ qidx,
                          const int* __restrict__ kidx, int m)
{
    int i = blockIdx.x * blockDim.x + threadIdx.x;
    if (i >= m * HC) return;
    int e = i >> 7, c = i & 127;
    float attn = g_ex[(e << 3) | (c & 7)];
    float val  = attn * g_v[kidx[e] * HC + c];
    atomicAdd(&g_agg[qidx[e] * HC + c], val);
}

// ---------------------------------------------------------------------------
// result = agg @ Wo
// ---------------------------------------------------------------------------
__global__ __launch_bounds__(128) void k_out(
    const float* __restrict__ Wo, float* __restrict__ out, int n)
{
    __shared__ float sa[8][HC];
    int t  = threadIdx.x;
    int nb = blockIdx.x * 8;
    int cnt = n - nb; if (cnt > 8) cnt = 8;

    for (int nn = 0; nn < cnt; nn++) sa[nn][t] = g_agg[(nb + nn) * HC + t];
    __syncthreads();

    float acc[8];
#pragma unroll
    for (int nn = 0; nn < 8; nn++) acc[nn] = 0.0f;

#pragma unroll 4
    for (int kk = 0; kk < HC; kk++) {
        float w = Wo[kk * HC + t];
#pragma unroll
        for (int nn = 0; nn < 8; nn++) acc[nn] += sa[nn][kk] * w;
    }
    for (int nn = 0; nn < cnt; nn++) out[(nb + nn) * HC + t] = acc[nn];
}

// ---------------------------------------------------------------------------
extern "C" void kernel_launch(void* const* d_in, const int* in_sizes, int n_in,
                              void* d_out, int out_size)
{
    const float* query  = (const float*)d_in[0];
    const float* key    = (const float*)d_in[1];
    const int*   qidx   = (const int*)  d_in[2];
    const int*   kidx   = (const int*)  d_in[3];
    const float* paired = (const float*)d_in[4];
    const float* Wq     = (const float*)d_in[5];
    const float* Wkv    = (const float*)d_in[6];
    const float* Wb     = (const float*)d_in[7];
    const float* Wo     = (const float*)d_in[8];

    int n = in_sizes[0] / HC;   // 50000
    int m = in_sizes[2];        // 400000

    float* out_result = (float*)d_out;           // n*HC
    float* out_logit  = (float*)d_out + n * HC;  // m*NH

    // k_edge needs 147456 B dynamic smem
    static const size_t EDGE_SMEM = (size_t)(HC * COLS + 32 * HC) * sizeof(float);
    cudaFuncSetAttribute(k_edge, cudaFuncAttributeMaxDynamicSharedMemorySize,
                         (int)EDGE_SMEM);

    int dev = 0, nsm = 148;
    cudaGetDevice(&dev);
    cudaDeviceGetAttribute(&nsm, cudaDevAttrMultiProcessorCount, dev);

    // 1. init
    {
        int tot = n * HC;
        k_init<<<(tot + 255) / 256, 256>>>(n);
    }
    // 2. projections
    k_proj<<<(n + 7) / 8, 128>>>(query, key, Wq, Wkv, n);
    // 3. fused bias GEMM + logits + segment max
    k_edge<<<nsm, 256, EDGE_SMEM>>>(paired, Wb, qidx, kidx, out_logit, m);
    // 4. exp + denom
    k_exp<<<(m * NH + 255) / 256, 256>>>(qidx, out_logit, m);
    // 5. normalize
    k_attn<<<(m * NH + 255) / 256, 256>>>(qidx, m);
    // 6. scatter agg
    k_scatter<<<(m * HC + 255) / 256, 256>>>(qidx, kidx, m);
    // 7. output projection
    k_out<<<(n + 7) / 8, 128>>>(Wo, out_result, n);
}

// round 2
// speedup vs baseline: 1.2129x; 1.2129x over previous
#include <cuda_runtime.h>
#include <math.h>

#define HC   128
#define NH   8
#define COLS 256
#define MAXN 50000
#define MAXM 400000

typedef unsigned long long ull;

// Scratch (device globals — no allocation allowed)
__device__ float g_q[MAXN * HC];
__device__ float g_k[MAXN * HC];
__device__ float g_v[MAXN * HC];
__device__ float g_agg[MAXN * HC];
__device__ float g_segmax[MAXN * NH];
__device__ float g_denom[MAXN * NH];
__device__ float g_ex[MAXM * NH];

// ---------------------------------------------------------------------------
// packed f32x2 helpers
// ---------------------------------------------------------------------------
__device__ __forceinline__ void ff2(ull& acc, ull a, ull b) {
    asm("fma.rn.f32x2 %0, %1, %2, %0;" : "+l"(acc) : "l"(a), "l"(b));
}
__device__ __forceinline__ ull dup2(float x) {
    ull d; asm("mov.b64 %0, {%1, %1};" : "=l"(d) : "f"(x)); return d;
}
__device__ __forceinline__ float sum2(ull a) {
    float x, y; asm("mov.b64 {%0, %1}, %2;" : "=f"(x), "=f"(y) : "l"(a));
    return x + y;
}
__device__ __forceinline__ void unpack2(ull a, float& x, float& y) {
    asm("mov.b64 {%0, %1}, %2;" : "=f"(x), "=f"(y) : "l"(a));
}

__device__ __forceinline__ void atomicMaxFloat(float* addr, float val) {
    if (val >= 0.0f) {
        atomicMax((int*)addr, __float_as_int(val));
    } else {
        atomicMin((unsigned int*)addr, __float_as_uint(val));
    }
}

// ---------------------------------------------------------------------------
// Init: zero agg & denom, segmax = -inf
// ---------------------------------------------------------------------------
__global__ void k_init(int n) {
    int i = blockIdx.x * blockDim.x + threadIdx.x;
    if (i < n * HC) g_agg[i] = 0.0f;
    if (i < n * NH) {
        g_denom[i] = 0.0f;
        ((unsigned int*)g_segmax)[i] = 0xFF800000u;  // -inf
    }
}

// ---------------------------------------------------------------------------
// Projections with FFMA2 over node pairs. 8 nodes / 128-thread block.
// Inputs staged transposed (k-major, node-minor, pad 10) so node pairs are
// contiguous 8B and loads are warp-broadcast.
// ---------------------------------------------------------------------------
__global__ __launch_bounds__(128) void k_proj(
    const float* __restrict__ query, const float* __restrict__ key,
    const float* __restrict__ Wq, const float* __restrict__ Wkv, int n)
{
    __shared__ float sqT[HC * 10];
    __shared__ float skT[HC * 10];
    int t  = threadIdx.x;
    int nb = blockIdx.x * 8;
    int cnt = n - nb; if (cnt > 8) cnt = 8;

    for (int nn = 0; nn < cnt; nn++) {
        sqT[t * 10 + nn] = query[(nb + nn) * HC + t];
        skT[t * 10 + nn] = key  [(nb + nn) * HC + t];
    }
    __syncthreads();

    ull aq[4], ak[4], av[4];
#pragma unroll
    for (int q = 0; q < 4; q++) { aq[q] = 0ull; ak[q] = 0ull; av[q] = 0ull; }

#pragma unroll 4
    for (int kk = 0; kk < HC; kk++) {
        ull wq = dup2(Wq [kk * HC   + t]);
        ull wk = dup2(Wkv[kk * COLS + t]);
        ull wv = dup2(Wkv[kk * COLS + HC + t]);
#pragma unroll
        for (int q = 0; q < 4; q++) {
            ull pq = *(const ull*)&sqT[kk * 10 + 2 * q];
            ull pk = *(const ull*)&skT[kk * 10 + 2 * q];
            ff2(aq[q], pq, wq);
            ff2(ak[q], pk, wk);
            ff2(av[q], pk, wv);
        }
    }
#pragma unroll
    for (int q = 0; q < 4; q++) {
        float x0, x1;
        if (2 * q < cnt) {
            unpack2(aq[q], x0, x1); g_q[(nb + 2 * q) * HC + t] = x0;
            if (2 * q + 1 < cnt)     g_q[(nb + 2 * q + 1) * HC + t] = x1;
            unpack2(ak[q], x0, x1); g_k[(nb + 2 * q) * HC + t] = x0;
            if (2 * q + 1 < cnt)     g_k[(nb + 2 * q + 1) * HC + t] = x1;
            unpack2(av[q], x0, x1); g_v[(nb + 2 * q) * HC + t] = x0;
            if (2 * q + 1 < cnt)     g_v[(nb + 2 * q + 1) * HC + t] = x1;
        }
    }
}

// ---------------------------------------------------------------------------
// Edge kernel: fused b = PR@Wb + bias-modulated logits + segment max.
// FFMA2 packed over the K dim. Wb in smem as (k even, k odd) float2 pairs.
// Warps: 4 edge-groups x 2 col-halves. Thread: 8 edges x 4 col-pairs.
// ---------------------------------------------------------------------------
__global__ __launch_bounds__(256, 1) void k_edge(
    const float* __restrict__ paired, const float* __restrict__ Wb,
    const int* __restrict__ qidx, const int* __restrict__ kidx,
    float* __restrict__ out_logit, int m)
{
    extern __shared__ float smem[];
    ull*   s_wb2  = (ull*)smem;                          // [64][256] k-pairs
    float* s_pr   = smem + 2 * 64 * COLS;                // [32][128]
    float* s_part = s_pr + 32 * HC;                      // [2][32][8]

    int tid  = threadIdx.x;
    int warp = tid >> 5;
    int lane = tid & 31;
    int we   = warp & 3;   // edge group 0..3
    int wc   = warp >> 2;  // col half 0..1

    // Stage Wb as k-pairs: s_wb2[k2*256+col] = (Wb[2k2][col], Wb[2k2+1][col])
    for (int i = tid; i < 64 * COLS; i += 256) {
        int k2 = i >> 8, col = i & 255;
        float2 t2 = make_float2(Wb[(2 * k2) * COLS + col],
                                Wb[(2 * k2 + 1) * COLS + col]);
        s_wb2[i] = *(ull*)&t2;
    }

    const ull* wbase = s_wb2 + wc * 128 + lane;
    const ulonglong2* s_pr2x = (const ulonglong2*)s_pr;

    int ntiles = (m + 31) >> 5;
    for (int tile = blockIdx.x; tile < ntiles; tile += gridDim.x) {
        int ebase = tile << 5;

        __syncthreads();  // prev readers done (covers Wb stage on iter 0)
        for (int ii = tid; ii < 32 * 32; ii += 256) {
            int e = ebase + (ii >> 5);
            float4 val = (e < m) ? ((const float4*)paired)[(long)e * 32 + (ii & 31)]
                                 : make_float4(0.f, 0.f, 0.f, 0.f);
            ((float4*)s_pr)[ii] = val;
        }
        __syncthreads();

        ull acc[8][4];
#pragma unroll
        for (int a = 0; a < 8; a++)
#pragma unroll
            for (int j = 0; j < 4; j++) acc[a][j] = 0ull;

#pragma unroll 2
        for (int k2 = 0; k2 < 64; k2 += 2) {
            ull w0[4], w1[4];
#pragma unroll
            for (int j = 0; j < 4; j++) {
                w0[j] = wbase[(k2)     * COLS + 32 * j];
                w1[j] = wbase[(k2 + 1) * COLS + 32 * j];
            }
#pragma unroll
            for (int a = 0; a < 8; a++) {
                ulonglong2 p = s_pr2x[(we * 8 + a) * 32 + (k2 >> 1)];
#pragma unroll
                for (int j = 0; j < 4; j++) {
                    ff2(acc[a][j], p.x, w0[j]);
                    ff2(acc[a][j], p.y, w1[j]);
                }
            }
        }

        // Epilogue: wc=0 holds bias_mul cols (c=32j+lane), wc=1 bias_add.
#pragma unroll
        for (int a = 0; a < 8; a++) {
            int el = we * 8 + a;
            int e  = ebase + el;
            float part = 0.0f;
            if (e < m) {  // uniform per warp
                int qi = qidx[e];
                if (wc == 0) {
                    int ki = kidx[e];
#pragma unroll
                    for (int j = 0; j < 4; j++) {
                        int c = 32 * j + lane;
                        float b  = sum2(acc[a][j]);
                        float qv = __ldg(&g_q[qi * HC + c]);
                        float kv = __ldg(&g_k[ki * HC + c]);
                        part += qv * fmaf(kv, b, kv);   // q*(k*(1+bm))
                    }
                } else {
#pragma unroll
                    for (int j = 0; j < 4; j++) {
                        int c = 32 * j + lane;
                        part += __ldg(&g_q[qi * HC + c]) * sum2(acc[a][j]);
                    }
                }
            }
            part += __shfl_xor_sync(0xffffffffu, part, 8);
            part += __shfl_xor_sync(0xffffffffu, part, 16);
            if (lane < 8) s_part[wc * 256 + el * 8 + lane] = part;
        }
        __syncthreads();

        // combine halves: 256 threads = 32 edges x 8 heads
        {
            int el = tid >> 3, h = tid & 7;
            int e  = ebase + el;
            if (e < m) {
                float lg = s_part[el * 8 + h] + s_part[256 + el * 8 + h];
                out_logit[e * NH + h] = lg;
                atomicMaxFloat(&g_segmax[qidx[e] * NH + h], lg);
            }
        }
    }
}

// ---------------------------------------------------------------------------
// exp + denom accumulation (float4 over 4 heads)
// ---------------------------------------------------------------------------
__global__ void k_exp(const int* __restrict__ qidx,
                      const float* __restrict__ logit, int m)
{
    int i = blockIdx.x * blockDim.x + threadIdx.x;
    if (i >= m * 2) return;
    int e = i >> 1, half = (i & 1) << 2;
    int qi = qidx[e];
    float4 lg = ((const float4*)logit)[i];
    float4 mx = *(const float4*)&g_segmax[qi * NH + half];
    float4 ex = make_float4(expf(lg.x - mx.x), expf(lg.y - mx.y),
                            expf(lg.z - mx.z), expf(lg.w - mx.w));
    ((float4*)g_ex)[i] = ex;
    atomicAdd((float4*)&g_denom[qi * NH + half], ex);
}

// ---------------------------------------------------------------------------
// normalize: ex -> attn (in place, float4)
// ---------------------------------------------------------------------------
__global__ void k_attn(const int* __restrict__ qidx, int m)
{
    int i = blockIdx.x * blockDim.x + threadIdx.x;
    if (i >= m * 2) return;
    int e = i >> 1, half = (i & 1) << 2;
    float4 dn = *(const float4*)&g_denom[qidx[e] * NH + half];
    float4 ex = ((const float4*)g_ex)[i];
    ex.x /= dn.x; ex.y /= dn.y; ex.z /= dn.z; ex.w /= dn.w;
    ((float4*)g_ex)[i] = ex;
}

// ---------------------------------------------------------------------------
// scatter: agg[qi] += attn * v[ki]  (float4 vector atomics)
// ---------------------------------------------------------------------------
__global__ void k_scatter(const int* __restrict__ qidx,
                          const int* __restrict__ kidx, int m)
{
    int i = blockIdx.x * blockDim.x + threadIdx.x;
    if (i >= m * 32) return;
    int e  = i >> 5;
    int c4 = (i & 31) << 2;                 // channel base, multiple of 4
    float4 v  = *(const float4*)&g_v[kidx[e] * HC + c4];
    float4 ex = *(const float4*)&g_ex[(e << 3) + (c4 & 7)];
    float4 val = make_float4(ex.x * v.x, ex.y * v.y, ex.z * v.z, ex.w * v.w);
    atomicAdd((float4*)&g_agg[qidx[e] * HC + c4], val);
}

// ---------------------------------------------------------------------------
// result = agg @ Wo  (FFMA2 over node pairs)
// ---------------------------------------------------------------------------
__global__ __launch_bounds__(128) void k_out(
    const float* __restrict__ Wo, float* __restrict__ out, int n)
{
    __shared__ float saT[HC * 10];
    int t  = threadIdx.x;
    int nb = blockIdx.x * 8;
    int cnt = n - nb; if (cnt > 8) cnt = 8;

    for (int nn = 0; nn < cnt; nn++)
        saT[t * 10 + nn] = g_agg[(nb + nn) * HC + t];
    __syncthreads();

    ull ao[4];
#pragma unroll
    for (int q = 0; q < 4; q++) ao[q] = 0ull;

#pragma unroll 4
    for (int kk = 0; kk < HC; kk++) {
        ull w = dup2(Wo[kk * HC + t]);
#pragma unroll
        for (int q = 0; q < 4; q++) {
            ull p = *(const ull*)&saT[kk * 10 + 2 * q];
            ff2(ao[q], p, w);
        }
    }
#pragma unroll
    for (int q = 0; q < 4; q++) {
        if (2 * q < cnt) {
            float x0, x1; unpack2(ao[q], x0, x1);
            out[(nb + 2 * q) * HC + t] = x0;
            if (2 * q + 1 < cnt) out[(nb + 2 * q + 1) * HC + t] = x1;
        }
    }
}

// ---------------------------------------------------------------------------
extern "C" void kernel_launch(void* const* d_in, const int* in_sizes, int n_in,
                              void* d_out, int out_size)
{
    const float* query  = (const float*)d_in[0];
    const float* key    = (const float*)d_in[1];
    const int*   qidx   = (const int*)  d_in[2];
    const int*   kidx   = (const int*)  d_in[3];
    const float* paired = (const float*)d_in[4];
    const float* Wq     = (const float*)d_in[5];
    const float* Wkv    = (const float*)d_in[6];
    const float* Wb     = (const float*)d_in[7];
    const float* Wo     = (const float*)d_in[8];

    int n = in_sizes[0] / HC;   // 50000
    int m = in_sizes[2];        // 400000

    float* out_result = (float*)d_out;           // n*HC
    float* out_logit  = (float*)d_out + n * HC;  // m*NH

    // k_edge dynamic smem: Wb pairs 128KB + PR tile 16KB + partials 2KB
    static const size_t EDGE_SMEM =
        (size_t)(2 * 64 * COLS + 32 * HC + 2 * 32 * NH) * sizeof(float);
    cudaFuncSetAttribute(k_edge, cudaFuncAttributeMaxDynamicSharedMemorySize,
                         (int)EDGE_SMEM);

    int dev = 0, nsm = 148;
    cudaGetDevice(&dev);
    cudaDeviceGetAttribute(&nsm, cudaDevAttrMultiProcessorCount, dev);

    // 1. init
    k_init<<<(n * HC + 255) / 256, 256>>>(n);
    // 2. projections
    k_proj<<<(n + 7) / 8, 128>>>(query, key, Wq, Wkv, n);
    // 3. fused bias GEMM + logits + segment max
    k_edge<<<nsm, 256, EDGE_SMEM>>>(paired, Wb, qidx, kidx, out_logit, m);
    // 4. exp + denom
    k_exp<<<(m * 2 + 255) / 256, 256>>>(qidx, out_logit, m);
    // 5. normalize
    k_attn<<<(m * 2 + 255) / 256, 256>>>(qidx, m);
    // 6. scatter agg
    k_scatter<<<(m * 32 + 255) / 256, 256>>>(qidx, kidx, m);
    // 7. output projection
    k_out<<<(n + 7) / 8, 128>>>(Wo, out_result, n);
}

// round 4
// speedup vs baseline: 2.4922x; 2.0548x over previous
#include <cuda_runtime.h>
#include <cuda_bf16.h>
#include <math.h>
#include <stdint.h>

#define HC   128
#define NH   8
#define COLS 256
#define MAXN 50000
#define MAXM 400000
#define TM   128   // edges per tile

typedef unsigned long long ull;

// Scratch (device globals — no allocation allowed)
__device__ float g_q[MAXN * HC];
__device__ float g_k[MAXN * HC];
__device__ float g_v[MAXN * HC];
__device__ float g_agg[MAXN * HC];
__device__ float g_segmax[MAXN * NH];
__device__ float g_denom[MAXN * NH];
__device__ float g_ex[MAXM * NH];

// ---------------------------------------------------------------------------
// packed f32x2 helpers (proj / out kernels)
// ---------------------------------------------------------------------------
__device__ __forceinline__ void ff2(ull& acc, ull a, ull b) {
    asm("fma.rn.f32x2 %0, %1, %2, %0;" : "+l"(acc) : "l"(a), "l"(b));
}
__device__ __forceinline__ ull dup2(float x) {
    ull d; asm("mov.b64 %0, {%1, %1};" : "=l"(d) : "f"(x)); return d;
}
__device__ __forceinline__ void unpack2(ull a, float& x, float& y) {
    asm("mov.b64 {%0, %1}, %2;" : "=f"(x), "=f"(y) : "l"(a));
}

__device__ __forceinline__ void atomicMaxFloat(float* addr, float val) {
    if (val >= 0.0f) atomicMax((int*)addr, __float_as_int(val));
    else             atomicMin((unsigned int*)addr, __float_as_uint(val));
}

__device__ __forceinline__ uint32_t smem_u32(const void* p) {
    uint32_t a;
    asm("{ .reg .u64 t; cvta.to.shared.u64 t, %1; cvt.u32.u64 %0, t; }"
        : "=r"(a) : "l"(p));
    return a;
}

// ---------------------------------------------------------------------------
// mma.sync / ldmatrix (base PTX ISA — valid for compute_103)
// ---------------------------------------------------------------------------
#define MMA_BF16(c, a, b) \
    asm volatile( \
        "mma.sync.aligned.m16n8k16.row.col.f32.bf16.bf16.f32 " \
        "{%0,%1,%2,%3}, {%4,%5,%6,%7}, {%8,%9}, {%0,%1,%2,%3};" \
        : "+f"((c)[0]), "+f"((c)[1]), "+f"((c)[2]), "+f"((c)[3]) \
        : "r"((a)[0]), "r"((a)[1]), "r"((a)[2]), "r"((a)[3]), \
          "r"((b)[0]), "r"((b)[1]))

#define LDSM_X4(r, addr) \
    asm volatile("ldmatrix.sync.aligned.m8n8.x4.shared.b16 {%0,%1,%2,%3}, [%4];" \
        : "=r"((r)[0]), "=r"((r)[1]), "=r"((r)[2]), "=r"((r)[3]) : "r"(addr))

// SMEM layout for k_edge_mma (bytes). Row pitch 136 bf16 = 272 B (17x16B,
// conflict-free ldmatrix).
#define PITCHB  272
#define SM_WB   0                       // [split 2][pass 2][nc 128][k 136] bf16
#define SM_WB_S 69632                   //   split stride
#define SM_WB_P 34816                   //   pass stride
#define SM_A    139264                  // [split 2][row 128][k 136] bf16
#define SM_A_S  34816
#define SM_PART 208896                  // [wn 2][128][8] f32
#define SM_QI   217088                  // [128] i32
#define SM_KI   217600                  // [128] i32
#define SM_EDGE_TOTAL 218112

// ---------------------------------------------------------------------------
// Init kernels
// ---------------------------------------------------------------------------
__global__ void k_init_max(int n) {
    int i = blockIdx.x * blockDim.x + threadIdx.x;
    if (i < n * NH) ((unsigned int*)g_segmax)[i] = 0xFF800000u;  // -inf
}
__global__ void k_init_agg(int n) {
    int i = blockIdx.x * blockDim.x + threadIdx.x;
    if (i < n * HC) g_agg[i] = 0.0f;
    if (i < n * NH) g_denom[i] = 0.0f;
}

// ---------------------------------------------------------------------------
// Projections with FFMA2 over node pairs (unchanged, passing)
// ---------------------------------------------------------------------------
__global__ __launch_bounds__(128) void k_proj(
    const float* __restrict__ query, const float* __restrict__ key,
    const float* __restrict__ Wq, const float* __restrict__ Wkv, int n)
{
    __shared__ float sqT[HC * 10];
    __shared__ float skT[HC * 10];
    int t  = threadIdx.x;
    int nb = blockIdx.x * 8;
    int cnt = n - nb; if (cnt > 8) cnt = 8;

    for (int nn = 0; nn < cnt; nn++) {
        sqT[t * 10 + nn] = query[(nb + nn) * HC + t];
        skT[t * 10 + nn] = key  [(nb + nn) * HC + t];
    }
    __syncthreads();

    ull aq[4], ak[4], av[4];
#pragma unroll
    for (int q = 0; q < 4; q++) { aq[q] = 0ull; ak[q] = 0ull; av[q] = 0ull; }

#pragma unroll 4
    for (int kk = 0; kk < HC; kk++) {
        ull wq = dup2(Wq [kk * HC   + t]);
        ull wk = dup2(Wkv[kk * COLS + t]);
        ull wv = dup2(Wkv[kk * COLS + HC + t]);
#pragma unroll
        for (int q = 0; q < 4; q++) {
            ull pq = *(const ull*)&sqT[kk * 10 + 2 * q];
            ull pk = *(const ull*)&skT[kk * 10 + 2 * q];
            ff2(aq[q], pq, wq);
            ff2(ak[q], pk, wk);
            ff2(av[q], pk, wv);
        }
    }
#pragma unroll
    for (int q = 0; q < 4; q++) {
        float x0, x1;
        if (2 * q < cnt) {
            unpack2(aq[q], x0, x1); g_q[(nb + 2 * q) * HC + t] = x0;
            if (2 * q + 1 < cnt)     g_q[(nb + 2 * q + 1) * HC + t] = x1;
            unpack2(ak[q], x0, x1); g_k[(nb + 2 * q) * HC + t] = x0;
            if (2 * q + 1 < cnt)     g_k[(nb + 2 * q + 1) * HC + t] = x1;
            unpack2(av[q], x0, x1); g_v[(nb + 2 * q) * HC + t] = x0;
            if (2 * q + 1 < cnt)     g_v[(nb + 2 * q + 1) * HC + t] = x1;
        }
    }
}

// ---------------------------------------------------------------------------
// Edge kernel: bf16 split-3 mma.sync GEMM (PR @ Wb) fused with bias-modulated
// logits + segment max. Persistent CTAs, 128 edges/tile.
//
// Column interleave in staged Wb^T: within a warp's 64-col range, nt even
// holds bias_mul, nt odd holds bias_add of the SAME channel block, so the
// epilogue loads each q/k pair exactly once.
//   nc = wn*64 + u*16 + bias*8 + off  -> channel = p*64 + wn*32 + u*8 + off,
//   Wb column = bias*128 + channel.
// ---------------------------------------------------------------------------
__global__ __launch_bounds__(256, 1) void k_edge_mma(
    const float* __restrict__ paired, const float* __restrict__ Wb,
    const int* __restrict__ qidx, const int* __restrict__ kidx,
    float* __restrict__ out_logit, int m)
{
    extern __shared__ char smem[];
    uint32_t sbase = smem_u32(smem);

    int tid  = threadIdx.x;
    int warp = tid >> 5;
    int lane = tid & 31;
    int wm   = warp >> 1;       // M-group 0..3 (32 edges each)
    int wn   = warp & 1;        // N-group 0..1 (64 cols each)
    int g    = lane >> 2;       // mma row group
    int t4   = lane & 3;        // mma col group

    int*   s_qi   = (int*)(smem + SM_QI);
    int*   s_ki   = (int*)(smem + SM_KI);
    float* s_part = (float*)(smem + SM_PART);

    // --- Stage Wb^T as bf16 hi/lo, interleaved columns, once per CTA ---
    for (int i = tid; i < 2 * 128 * 64; i += 256) {
        int kp = i & 63;            // k pair index
        int nc = (i >> 6) & 127;
        int p  = i >> 13;
        int wn_ = nc >> 6, ln = nc & 63;
        int u = ln >> 4, bias = (ln >> 3) & 1, off = ln & 7;
        int ch   = p * 64 + wn_ * 32 + u * 8 + off;
        int wcol = bias * 128 + ch;
        float w0 = Wb[(2 * kp)     * COLS + wcol];
        float w1 = Wb[(2 * kp + 1) * COLS + wcol];
        __nv_bfloat162 hi2 = __floats2bfloat162_rn(w0, w1);
        float r0 = w0 - __bfloat162float(hi2.x);
        float r1 = w1 - __bfloat162float(hi2.y);
        __nv_bfloat162 lo2 = __floats2bfloat162_rn(r0, r1);
        size_t off_b = (size_t)p * SM_WB_P + (size_t)nc * PITCHB + (size_t)kp * 4;
        *(uint32_t*)(smem + SM_WB + off_b)           = *(uint32_t*)&hi2;
        *(uint32_t*)(smem + SM_WB + SM_WB_S + off_b) = *(uint32_t*)&lo2;
    }

    // per-lane ldmatrix offsets
    uint32_t aoff = (uint32_t)(((lane & 7) + 8 * ((lane >> 3) & 1)) * PITCHB
                               + ((lane >> 4) & 1) * 16);
    uint32_t boff = (uint32_t)(((lane & 7) + 8 * ((lane >> 4) & 1)) * PITCHB
                               + ((lane >> 3) & 1) * 16);
    uint32_t a_base = sbase + SM_A  + (uint32_t)(wm * 32) * PITCHB + aoff;
    uint32_t b_base = sbase + SM_WB + (uint32_t)(wn * 64) * PITCHB + boff;

    int ntiles = (m + TM - 1) / TM;
    for (int tile = blockIdx.x; tile < ntiles; tile += gridDim.x) {
        int ebase = tile * TM;
        __syncthreads();  // prev-tile readers done

        // --- Stage A tile (PR -> bf16 hi/lo) + indices ---
        for (int i = tid; i < TM * 64; i += 256) {
            int r = i >> 6, cp = i & 63;
            int e = ebase + r;
            float2 x = (e < m) ? ((const float2*)paired)[(size_t)e * 64 + cp]
                               : make_float2(0.f, 0.f);
            __nv_bfloat162 hi2 = __floats2bfloat162_rn(x.x, x.y);
            float r0 = x.x - __bfloat162float(hi2.x);
            float r1 = x.y - __bfloat162float(hi2.y);
            __nv_bfloat162 lo2 = __floats2bfloat162_rn(r0, r1);
            size_t off_a = (size_t)r * PITCHB + (size_t)cp * 4;
            *(uint32_t*)(smem + SM_A + off_a)          = *(uint32_t*)&hi2;
            *(uint32_t*)(smem + SM_A + SM_A_S + off_a) = *(uint32_t*)&lo2;
        }
        if (tid < TM) {
            int e = ebase + tid;
            s_qi[tid] = (e < m) ? qidx[e] : 0;
            s_ki[tid] = (e < m) ? kidx[e] : 0;
        }
        __syncthreads();

        float part[4][2];
#pragma unroll
        for (int a = 0; a < 4; a++) { part[a][0] = 0.f; part[a][1] = 0.f; }

#pragma unroll
        for (int p = 0; p < 2; p++) {
            float acc[2][8][4];
#pragma unroll
            for (int mt = 0; mt < 2; mt++)
#pragma unroll
                for (int nt = 0; nt < 8; nt++)
#pragma unroll
                    for (int el = 0; el < 4; el++) acc[mt][nt][el] = 0.f;

#pragma unroll 2
            for (int ks = 0; ks < 8; ks++) {
                uint32_t bh[8][2], bl[8][2], ah[2][4], al[2][4];
                uint32_t bk = b_base + (uint32_t)p * SM_WB_P + (uint32_t)ks * 32;
#pragma unroll
                for (int u2 = 0; u2 < 4; u2++) {
                    uint32_t tmp[4];
                    LDSM_X4(tmp, bk + (uint32_t)(u2 * 16) * PITCHB);
                    bh[2*u2][0] = tmp[0]; bh[2*u2][1] = tmp[1];
                    bh[2*u2+1][0] = tmp[2]; bh[2*u2+1][1] = tmp[3];
                    LDSM_X4(tmp, bk + SM_WB_S + (uint32_t)(u2 * 16) * PITCHB);
                    bl[2*u2][0] = tmp[0]; bl[2*u2][1] = tmp[1];
                    bl[2*u2+1][0] = tmp[2]; bl[2*u2+1][1] = tmp[3];
                }
                uint32_t ak_ = a_base + (uint32_t)ks * 32;
#pragma unroll
                for (int mt = 0; mt < 2; mt++) {
                    LDSM_X4(ah[mt], ak_ + (uint32_t)(mt * 16) * PITCHB);
                    LDSM_X4(al[mt], ak_ + SM_A_S + (uint32_t)(mt * 16) * PITCHB);
                }
#pragma unroll
                for (int mt = 0; mt < 2; mt++)
#pragma unroll
                    for (int nt = 0; nt < 8; nt++) {
                        MMA_BF16(acc[mt][nt], ah[mt], bh[nt]);
                        MMA_BF16(acc[mt][nt], ah[mt], bl[nt]);
                        MMA_BF16(acc[mt][nt], al[mt], bh[nt]);
                    }
            }

            // --- Epilogue for this pass: channels p*64 + wn*32 + u*8 + 2t+j ---
#pragma unroll
            for (int mt = 0; mt < 2; mt++)
#pragma unroll
                for (int rh = 0; rh < 2; rh++) {
                    int eli = wm * 32 + mt * 16 + g + rh * 8;
                    const float* qrow = g_q + (size_t)s_qi[eli] * HC;
                    const float* krow = g_k + (size_t)s_ki[eli] * HC;
#pragma unroll
                    for (int u = 0; u < 4; u++) {
                        int c = p * 64 + wn * 32 + u * 8 + t4 * 2;
                        float2 q2 = *(const float2*)(qrow + c);
                        float2 k2 = *(const float2*)(krow + c);
                        float bm0 = acc[mt][2*u][rh*2],   bm1 = acc[mt][2*u][rh*2+1];
                        float ba0 = acc[mt][2*u+1][rh*2], ba1 = acc[mt][2*u+1][rh*2+1];
                        float qk0 = q2.x * k2.x;
                        float qk1 = q2.y * k2.y;
                        part[mt*2+rh][0] += fmaf(qk0, bm0, qk0) + q2.x * ba0;
                        part[mt*2+rh][1] += fmaf(qk1, bm1, qk1) + q2.y * ba1;
                    }
                }
        }

        // write partials: heads 2t, 2t+1
#pragma unroll
        for (int mt = 0; mt < 2; mt++)
#pragma unroll
            for (int rh = 0; rh < 2; rh++) {
                int eli = wm * 32 + mt * 16 + g + rh * 8;
                float2* sp = (float2*)&s_part[wn * 1024 + eli * 8 + t4 * 2];
                *sp = make_float2(part[mt*2+rh][0], part[mt*2+rh][1]);
            }
        __syncthreads();

        // combine halves, emit logit + segment max
#pragma unroll
        for (int j = 0; j < 4; j++) {
            int i  = tid + j * 256;
            int el = i >> 3, h = i & 7;
            int e  = ebase + el;
            if (e < m) {
                float lg = s_part[i] + s_part[1024 + i];
                out_logit[e * NH + h] = lg;
                atomicMaxFloat(&g_segmax[s_qi[el] * NH + h], lg);
            }
        }
    }
}

// ---------------------------------------------------------------------------
// exp + denom accumulation (float4 over 4 heads)
// ---------------------------------------------------------------------------
__global__ void k_exp(const int* __restrict__ qidx,
                      const float* __restrict__ logit, int m)
{
    int i = blockIdx.x * blockDim.x + threadIdx.x;
    if (i >= m * 2) return;
    int e = i >> 1, half = (i & 1) << 2;
    int qi = qidx[e];
    float4 lg = ((const float4*)logit)[i];
    float4 mx = *(const float4*)&g_segmax[qi * NH + half];
    float4 ex = make_float4(expf(lg.x - mx.x), expf(lg.y - mx.y),
                            expf(lg.z - mx.z), expf(lg.w - mx.w));
    ((float4*)g_ex)[i] = ex;
    atomicAdd((float4*)&g_denom[qi * NH + half], ex);
}

// ---------------------------------------------------------------------------
// normalize: ex -> attn (in place, float4)
// ---------------------------------------------------------------------------
__global__ void k_attn(const int* __restrict__ qidx, int m)
{
    int i = blockIdx.x * blockDim.x + threadIdx.x;
    if (i >= m * 2) return;
    int e = i >> 1, half = (i & 1) << 2;
    float4 dn = *(const float4*)&g_denom[qidx[e] * NH + half];
    float4 ex = ((const float4*)g_ex)[i];
    ex.x /= dn.x; ex.y /= dn.y; ex.z /= dn.z; ex.w /= dn.w;
    ((float4*)g_ex)[i] = ex;
}

// ---------------------------------------------------------------------------
// scatter: agg[qi] += attn * v[ki]  (float4 vector atomics)
// ---------------------------------------------------------------------------
__global__ void k_scatter(const int* __restrict__ qidx,
                          const int* __restrict__ kidx, int m)
{
    int i = blockIdx.x * blockDim.x + threadIdx.x;
    if (i >= m * 32) return;
    int e  = i >> 5;
    int c4 = (i & 31) << 2;
    float4 v  = *(const float4*)&g_v[kidx[e] * HC + c4];
    float4 ex = *(const float4*)&g_ex[(e << 3) + (c4 & 7)];
    float4 val = make_float4(ex.x * v.x, ex.y * v.y, ex.z * v.z, ex.w * v.w);
    atomicAdd((float4*)&g_agg[qidx[e] * HC + c4], val);
}

// ---------------------------------------------------------------------------
// result = agg @ Wo  (FFMA2 over node pairs)
// ---------------------------------------------------------------------------
__global__ __launch_bounds__(128) void k_out(
    const float* __restrict__ Wo, float* __restrict__ out, int n)
{
    __shared__ float saT[HC * 10];
    int t  = threadIdx.x;
    int nb = blockIdx.x * 8;
    int cnt = n - nb; if (cnt > 8) cnt = 8;

    for (int nn = 0; nn < cnt; nn++)
        saT[t * 10 + nn] = g_agg[(nb + nn) * HC + t];
    __syncthreads();

    ull ao[4];
#pragma unroll
    for (int q = 0; q < 4; q++) ao[q] = 0ull;

#pragma unroll 4
    for (int kk = 0; kk < HC; kk++) {
        ull w = dup2(Wo[kk * HC + t]);
#pragma unroll
        for (int q = 0; q < 4; q++) {
            ull p = *(const ull*)&saT[kk * 10 + 2 * q];
            ff2(ao[q], p, w);
        }
    }
#pragma unroll
    for (int q = 0; q < 4; q++) {
        if (2 * q < cnt) {
            float x0, x1; unpack2(ao[q], x0, x1);
            out[(nb + 2 * q) * HC + t] = x0;
            if (2 * q + 1 < cnt) out[(nb + 2 * q + 1) * HC + t] = x1;
        }
    }
}

// ---------------------------------------------------------------------------
extern "C" void kernel_launch(void* const* d_in, const int* in_sizes, int n_in,
                              void* d_out, int out_size)
{
    const float* query  = (const float*)d_in[0];
    const float* key    = (const float*)d_in[1];
    const int*   qidx   = (const int*)  d_in[2];
    const int*   kidx   = (const int*)  d_in[3];
    const float* paired = (const float*)d_in[4];
    const float* Wq     = (const float*)d_in[5];
    const float* Wkv    = (const float*)d_in[6];
    const float* Wb     = (const float*)d_in[7];
    const float* Wo     = (const float*)d_in[8];

    int n = in_sizes[0] / HC;   // 50000
    int m = in_sizes[2];        // 400000

    float* out_result = (float*)d_out;           // n*HC
    float* out_logit  = (float*)d_out + n * HC;  // m*NH

    cudaFuncSetAttribute(k_edge_mma, cudaFuncAttributeMaxDynamicSharedMemorySize,
                         SM_EDGE_TOTAL);

    int dev = 0, nsm = 148;
    cudaGetDevice(&dev);
    cudaDeviceGetAttribute(&nsm, cudaDevAttrMultiProcessorCount, dev);

    int ntiles = (m + TM - 1) / TM;
    int egrid  = ntiles < nsm ? ntiles : nsm;

    // Launch order keeps k_edge_mma in the profiled (4th) slot.
    k_init_max<<<(n * NH + 255) / 256, 256>>>(n);                        // 1
    k_proj<<<(n + 7) / 8, 128>>>(query, key, Wq, Wkv, n);                // 2
    k_init_agg<<<(n * HC + 255) / 256, 256>>>(n);                        // 3
    k_edge_mma<<<egrid, 256, SM_EDGE_TOTAL>>>(paired, Wb, qidx, kidx,    // 4
                                              out_logit, m);
    k_exp<<<(m * 2 + 255) / 256, 256>>>(qidx, out_logit, m);             // 5
    k_attn<<<(m * 2 + 255) / 256, 256>>>(qidx, m);                       // 6
    k_scatter<<<(m * 32 + 255) / 256, 256>>>(qidx, kidx, m);             // 7
    k_out<<<(n + 7) / 8, 128>>>(Wo, out_result, n);                      // 8
}

// round 5
// speedup vs baseline: 2.7311x; 1.0958x over previous
#include <cuda_runtime.h>
#include <cuda_bf16.h>
#include <math.h>
#include <stdint.h>

#define HC   128
#define NH   8
#define COLS 256
#define MAXN 50000
#define MAXM 400000
#define TM   128   // edges per tile

typedef unsigned long long ull;

// Scratch (device globals — no allocation allowed)
__device__ float g_q[MAXN * HC];
__device__ float g_k[MAXN * HC];
__device__ float g_v[MAXN * HC];
__device__ float g_agg[MAXN * HC];
__device__ float g_segmax[MAXN * NH];
__device__ float g_denom[MAXN * NH];
__device__ float g_ex[MAXM * NH];

// ---------------------------------------------------------------------------
// packed f32x2 helpers (proj / out kernels)
// ---------------------------------------------------------------------------
__device__ __forceinline__ void ff2(ull& acc, ull a, ull b) {
    asm("fma.rn.f32x2 %0, %1, %2, %0;" : "+l"(acc) : "l"(a), "l"(b));
}
__device__ __forceinline__ ull dup2(float x) {
    ull d; asm("mov.b64 %0, {%1, %1};" : "=l"(d) : "f"(x)); return d;
}
__device__ __forceinline__ void unpack2(ull a, float& x, float& y) {
    asm("mov.b64 {%0, %1}, %2;" : "=f"(x), "=f"(y) : "l"(a));
}

__device__ __forceinline__ void atomicMaxFloat(float* addr, float val) {
    if (val >= 0.0f) atomicMax((int*)addr, __float_as_int(val));
    else             atomicMin((unsigned int*)addr, __float_as_uint(val));
}

__device__ __forceinline__ uint32_t smem_u32(const void* p) {
    uint32_t a;
    asm("{ .reg .u64 t; cvta.to.shared.u64 t, %1; cvt.u32.u64 %0, t; }"
        : "=r"(a) : "l"(p));
    return a;
}

// ---------------------------------------------------------------------------
// mma.sync / ldmatrix (base PTX ISA — valid for compute_103)
// ---------------------------------------------------------------------------
#define MMA_BF16(c, a, b) \
    asm volatile( \
        "mma.sync.aligned.m16n8k16.row.col.f32.bf16.bf16.f32 " \
        "{%0,%1,%2,%3}, {%4,%5,%6,%7}, {%8,%9}, {%0,%1,%2,%3};" \
        : "+f"((c)[0]), "+f"((c)[1]), "+f"((c)[2]), "+f"((c)[3]) \
        : "r"((a)[0]), "r"((a)[1]), "r"((a)[2]), "r"((a)[3]), \
          "r"((b)[0]), "r"((b)[1]))

#define LDSM_X4(r, addr) \
    asm volatile("ldmatrix.sync.aligned.m8n8.x4.shared.b16 {%0,%1,%2,%3}, [%4];" \
        : "=r"((r)[0]), "=r"((r)[1]), "=r"((r)[2]), "=r"((r)[3]) : "r"(addr))

// SMEM layout for k_edge_mma (bytes). Row pitch 136 bf16 = 272 B (17x16B,
// conflict-free ldmatrix).
#define PITCHB  272
#define SM_WB   0                       // [split 2][pass 2][nc 128][k 136] bf16
#define SM_WB_S 69632                   //   split stride
#define SM_WB_P 34816                   //   pass stride
#define SM_A    139264                  // [split 2][row 128][k 136] bf16
#define SM_A_S  34816
#define SM_PART 208896                  // [wn 4][128][8] f32
#define SM_QI   225280                  // [128] i32
#define SM_KI   225792                  // [128] i32
#define SM_EDGE_TOTAL 226304

// ---------------------------------------------------------------------------
// Init kernels
// ---------------------------------------------------------------------------
__global__ void k_init_max(int n) {
    int i = blockIdx.x * blockDim.x + threadIdx.x;
    if (i < n * NH) ((unsigned int*)g_segmax)[i] = 0xFF800000u;  // -inf
}
__global__ void k_init_agg(int n) {
    int i = blockIdx.x * blockDim.x + threadIdx.x;
    if (i < n * HC) g_agg[i] = 0.0f;
    if (i < n * NH) g_denom[i] = 0.0f;
}

// ---------------------------------------------------------------------------
// Projections with FFMA2 over node pairs (unchanged, passing)
// ---------------------------------------------------------------------------
__global__ __launch_bounds__(128) void k_proj(
    const float* __restrict__ query, const float* __restrict__ key,
    const float* __restrict__ Wq, const float* __restrict__ Wkv, int n)
{
    __shared__ float sqT[HC * 10];
    __shared__ float skT[HC * 10];
    int t  = threadIdx.x;
    int nb = blockIdx.x * 8;
    int cnt = n - nb; if (cnt > 8) cnt = 8;

    for (int nn = 0; nn < cnt; nn++) {
        sqT[t * 10 + nn] = query[(nb + nn) * HC + t];
        skT[t * 10 + nn] = key  [(nb + nn) * HC + t];
    }
    __syncthreads();

    ull aq[4], ak[4], av[4];
#pragma unroll
    for (int q = 0; q < 4; q++) { aq[q] = 0ull; ak[q] = 0ull; av[q] = 0ull; }

#pragma unroll 4
    for (int kk = 0; kk < HC; kk++) {
        ull wq = dup2(Wq [kk * HC   + t]);
        ull wk = dup2(Wkv[kk * COLS + t]);
        ull wv = dup2(Wkv[kk * COLS + HC + t]);
#pragma unroll
        for (int q = 0; q < 4; q++) {
            ull pq = *(const ull*)&sqT[kk * 10 + 2 * q];
            ull pk = *(const ull*)&skT[kk * 10 + 2 * q];
            ff2(aq[q], pq, wq);
            ff2(ak[q], pk, wk);
            ff2(av[q], pk, wv);
        }
    }
#pragma unroll
    for (int q = 0; q < 4; q++) {
        float x0, x1;
        if (2 * q < cnt) {
            unpack2(aq[q], x0, x1); g_q[(nb + 2 * q) * HC + t] = x0;
            if (2 * q + 1 < cnt)     g_q[(nb + 2 * q + 1) * HC + t] = x1;
            unpack2(ak[q], x0, x1); g_k[(nb + 2 * q) * HC + t] = x0;
            if (2 * q + 1 < cnt)     g_k[(nb + 2 * q + 1) * HC + t] = x1;
            unpack2(av[q], x0, x1); g_v[(nb + 2 * q) * HC + t] = x0;
            if (2 * q + 1 < cnt)     g_v[(nb + 2 * q + 1) * HC + t] = x1;
        }
    }
}

// ---------------------------------------------------------------------------
// Edge kernel: bf16 split-3 mma.sync GEMM (PR @ Wb) fused with bias-modulated
// logits + segment max. Persistent CTAs, 128 edges/tile, 16 warps,
// warp tile 32 edges x 32 staged cols (16 channels, mul/add interleaved).
//
//   staged col nc (within pass p) = wn*32 + u*16 + bias*8 + off
//   channel  = p*64 + wn*16 + u*8 + off ; Wb column = bias*128 + channel
// ---------------------------------------------------------------------------
__global__ __launch_bounds__(512, 1) void k_edge_mma(
    const float* __restrict__ paired, const float* __restrict__ Wb,
    const int* __restrict__ qidx, const int* __restrict__ kidx,
    float* __restrict__ out_logit, int m)
{
    extern __shared__ char smem[];
    uint32_t sbase = smem_u32(smem);

    int tid  = threadIdx.x;
    int warp = tid >> 5;
    int lane = tid & 31;
    int wm   = warp >> 2;       // M-group 0..3 (32 edges each)
    int wn   = warp & 3;        // N-group 0..3 (32 staged cols each)
    int g    = lane >> 2;       // mma row group
    int t4   = lane & 3;        // mma col group

    int*   s_qi   = (int*)(smem + SM_QI);
    int*   s_ki   = (int*)(smem + SM_KI);
    float* s_part = (float*)(smem + SM_PART);

    // --- Stage Wb^T as bf16 hi/lo, interleaved columns, once per CTA ---
    for (int i = tid; i < 2 * 128 * 64; i += 512) {
        int kp = i & 63;            // k pair index
        int nc = (i >> 6) & 127;
        int p  = i >> 13;
        int wn_ = nc >> 5, ln = nc & 31;
        int u = ln >> 4, bias = (ln >> 3) & 1, off = ln & 7;
        int ch   = p * 64 + wn_ * 16 + u * 8 + off;
        int wcol = bias * 128 + ch;
        float w0 = Wb[(2 * kp)     * COLS + wcol];
        float w1 = Wb[(2 * kp + 1) * COLS + wcol];
        __nv_bfloat162 hi2 = __floats2bfloat162_rn(w0, w1);
        float r0 = w0 - __bfloat162float(hi2.x);
        float r1 = w1 - __bfloat162float(hi2.y);
        __nv_bfloat162 lo2 = __floats2bfloat162_rn(r0, r1);
        size_t off_b = (size_t)p * SM_WB_P + (size_t)nc * PITCHB + (size_t)kp * 4;
        *(uint32_t*)(smem + SM_WB + off_b)           = *(uint32_t*)&hi2;
        *(uint32_t*)(smem + SM_WB + SM_WB_S + off_b) = *(uint32_t*)&lo2;
    }

    // per-lane ldmatrix offsets
    uint32_t aoff = (uint32_t)(((lane & 7) + 8 * ((lane >> 3) & 1)) * PITCHB
                               + ((lane >> 4) & 1) * 16);
    uint32_t boff = (uint32_t)(((lane & 7) + 8 * ((lane >> 4) & 1)) * PITCHB
                               + ((lane >> 3) & 1) * 16);
    uint32_t a_base = sbase + SM_A  + (uint32_t)(wm * 32) * PITCHB + aoff;
    uint32_t b_base = sbase + SM_WB + (uint32_t)(wn * 32) * PITCHB + boff;

    int ntiles = (m + TM - 1) / TM;
    for (int tile = blockIdx.x; tile < ntiles; tile += gridDim.x) {
        int ebase = tile * TM;
        __syncthreads();  // prev-tile readers done

        // --- Stage A tile (PR -> bf16 hi/lo) + indices ---
        for (int i = tid; i < TM * 64; i += 512) {
            int r = i >> 6, cp = i & 63;
            int e = ebase + r;
            float2 x = (e < m) ? ((const float2*)paired)[(size_t)e * 64 + cp]
                               : make_float2(0.f, 0.f);
            __nv_bfloat162 hi2 = __floats2bfloat162_rn(x.x, x.y);
            float r0 = x.x - __bfloat162float(hi2.x);
            float r1 = x.y - __bfloat162float(hi2.y);
            __nv_bfloat162 lo2 = __floats2bfloat162_rn(r0, r1);
            size_t off_a = (size_t)r * PITCHB + (size_t)cp * 4;
            *(uint32_t*)(smem + SM_A + off_a)          = *(uint32_t*)&hi2;
            *(uint32_t*)(smem + SM_A + SM_A_S + off_a) = *(uint32_t*)&lo2;
        }
        if (tid < TM) {
            int e = ebase + tid;
            s_qi[tid] = (e < m) ? qidx[e] : 0;
            s_ki[tid] = (e < m) ? kidx[e] : 0;
        }
        __syncthreads();

        float part[4][2];
#pragma unroll
        for (int a = 0; a < 4; a++) { part[a][0] = 0.f; part[a][1] = 0.f; }

#pragma unroll
        for (int p = 0; p < 2; p++) {
            float acc[2][4][4];
#pragma unroll
            for (int mt = 0; mt < 2; mt++)
#pragma unroll
                for (int nt = 0; nt < 4; nt++)
#pragma unroll
                    for (int el = 0; el < 4; el++) acc[mt][nt][el] = 0.f;

#pragma unroll 2
            for (int ks = 0; ks < 8; ks++) {
                uint32_t bh[4][2], bl[4][2], ah[2][4], al[2][4];
                uint32_t bk = b_base + (uint32_t)p * SM_WB_P + (uint32_t)ks * 32;
#pragma unroll
                for (int u2 = 0; u2 < 2; u2++) {
                    uint32_t tmp[4];
                    LDSM_X4(tmp, bk + (uint32_t)(u2 * 16) * PITCHB);
                    bh[2*u2][0] = tmp[0]; bh[2*u2][1] = tmp[1];
                    bh[2*u2+1][0] = tmp[2]; bh[2*u2+1][1] = tmp[3];
                    LDSM_X4(tmp, bk + SM_WB_S + (uint32_t)(u2 * 16) * PITCHB);
                    bl[2*u2][0] = tmp[0]; bl[2*u2][1] = tmp[1];
                    bl[2*u2+1][0] = tmp[2]; bl[2*u2+1][1] = tmp[3];
                }
                uint32_t ak_ = a_base + (uint32_t)ks * 32;
#pragma unroll
                for (int mt = 0; mt < 2; mt++) {
                    LDSM_X4(ah[mt], ak_ + (uint32_t)(mt * 16) * PITCHB);
                    LDSM_X4(al[mt], ak_ + SM_A_S + (uint32_t)(mt * 16) * PITCHB);
                }
#pragma unroll
                for (int mt = 0; mt < 2; mt++)
#pragma unroll
                    for (int nt = 0; nt < 4; nt++) {
                        MMA_BF16(acc[mt][nt], ah[mt], bh[nt]);
                        MMA_BF16(acc[mt][nt], ah[mt], bl[nt]);
                        MMA_BF16(acc[mt][nt], al[mt], bh[nt]);
                    }
            }

            // --- Epilogue for this pass: channels p*64 + wn*16 + u*8 + 2t4+j ---
#pragma unroll
            for (int mt = 0; mt < 2; mt++)
#pragma unroll
                for (int rh = 0; rh < 2; rh++) {
                    int eli = wm * 32 + mt * 16 + g + rh * 8;
                    const float* qrow = g_q + (size_t)s_qi[eli] * HC;
                    const float* krow = g_k + (size_t)s_ki[eli] * HC;
#pragma unroll
                    for (int u = 0; u < 2; u++) {
                        int c = p * 64 + wn * 16 + u * 8 + t4 * 2;
                        float2 q2 = *(const float2*)(qrow + c);
                        float2 k2 = *(const float2*)(krow + c);
                        float bm0 = acc[mt][2*u][rh*2],   bm1 = acc[mt][2*u][rh*2+1];
                        float ba0 = acc[mt][2*u+1][rh*2], ba1 = acc[mt][2*u+1][rh*2+1];
                        float qk0 = q2.x * k2.x;
                        float qk1 = q2.y * k2.y;
                        part[mt*2+rh][0] += fmaf(qk0, bm0, qk0) + q2.x * ba0;
                        part[mt*2+rh][1] += fmaf(qk1, bm1, qk1) + q2.y * ba1;
                    }
                }
        }

        // write partials: heads 2t4, 2t4+1
#pragma unroll
        for (int mt = 0; mt < 2; mt++)
#pragma unroll
            for (int rh = 0; rh < 2; rh++) {
                int eli = wm * 32 + mt * 16 + g + rh * 8;
                float2* sp = (float2*)&s_part[wn * 1024 + eli * 8 + t4 * 2];
                *sp = make_float2(part[mt*2+rh][0], part[mt*2+rh][1]);
            }
        __syncthreads();

        // combine 4 N-groups, emit logit + segment max
#pragma unroll
        for (int j = 0; j < 2; j++) {
            int i  = tid + j * 512;
            int el = i >> 3, h = i & 7;
            int e  = ebase + el;
            if (e < m) {
                float lg = (s_part[i] + s_part[1024 + i])
                         + (s_part[2048 + i] + s_part[3072 + i]);
                out_logit[e * NH + h] = lg;
                atomicMaxFloat(&g_segmax[s_qi[el] * NH + h], lg);
            }
        }
    }
}

// ---------------------------------------------------------------------------
// exp + denom accumulation (float4 over 4 heads)
// ---------------------------------------------------------------------------
__global__ void k_exp(const int* __restrict__ qidx,
                      const float* __restrict__ logit, int m)
{
    int i = blockIdx.x * blockDim.x + threadIdx.x;
    if (i >= m * 2) return;
    int e = i >> 1, half = (i & 1) << 2;
    int qi = qidx[e];
    float4 lg = ((const float4*)logit)[i];
    float4 mx = *(const float4*)&g_segmax[qi * NH + half];
    float4 ex = make_float4(expf(lg.x - mx.x), expf(lg.y - mx.y),
                            expf(lg.z - mx.z), expf(lg.w - mx.w));
    ((float4*)g_ex)[i] = ex;
    atomicAdd((float4*)&g_denom[qi * NH + half], ex);
}

// ---------------------------------------------------------------------------
// normalize: ex -> attn (in place, float4)
// ---------------------------------------------------------------------------
__global__ void k_attn(const int* __restrict__ qidx, int m)
{
    int i = blockIdx.x * blockDim.x + threadIdx.x;
    if (i >= m * 2) return;
    int e = i >> 1, half = (i & 1) << 2;
    float4 dn = *(const float4*)&g_denom[qidx[e] * NH + half];
    float4 ex = ((const float4*)g_ex)[i];
    ex.x /= dn.x; ex.y /= dn.y; ex.z /= dn.z; ex.w /= dn.w;
    ((float4*)g_ex)[i] = ex;
}

// ---------------------------------------------------------------------------
// scatter: agg[qi] += attn * v[ki]  (float4 vector atomics)
// ---------------------------------------------------------------------------
__global__ void k_scatter(const int* __restrict__ qidx,
                          const int* __restrict__ kidx, int m)
{
    int i = blockIdx.x * blockDim.x + threadIdx.x;
    if (i >= m * 32) return;
    int e  = i >> 5;
    int c4 = (i & 31) << 2;
    float4 v  = *(const float4*)&g_v[kidx[e] * HC + c4];
    float4 ex = *(const float4*)&g_ex[(e << 3) + (c4 & 7)];
    float4 val = make_float4(ex.x * v.x, ex.y * v.y, ex.z * v.z, ex.w * v.w);
    atomicAdd((float4*)&g_agg[qidx[e] * HC + c4], val);
}

// ---------------------------------------------------------------------------
// result = agg @ Wo  (FFMA2 over node pairs)
// ---------------------------------------------------------------------------
__global__ __launch_bounds__(128) void k_out(
    const float* __restrict__ Wo, float* __restrict__ out, int n)
{
    __shared__ float saT[HC * 10];
    int t  = threadIdx.x;
    int nb = blockIdx.x * 8;
    int cnt = n - nb; if (cnt > 8) cnt = 8;

    for (int nn = 0; nn < cnt; nn++)
        saT[t * 10 + nn] = g_agg[(nb + nn) * HC + t];
    __syncthreads();

    ull ao[4];
#pragma unroll
    for (int q = 0; q < 4; q++) ao[q] = 0ull;

#pragma unroll 4
    for (int kk = 0; kk < HC; kk++) {
        ull w = dup2(Wo[kk * HC + t]);
#pragma unroll
        for (int q = 0; q < 4; q++) {
            ull p = *(const ull*)&saT[kk * 10 + 2 * q];
            ff2(ao[q], p, w);
        }
    }
#pragma unroll
    for (int q = 0; q < 4; q++) {
        if (2 * q < cnt) {
            float x0, x1; unpack2(ao[q], x0, x1);
            out[(nb + 2 * q) * HC + t] = x0;
            if (2 * q + 1 < cnt) out[(nb + 2 * q + 1) * HC + t] = x1;
        }
    }
}

// ---------------------------------------------------------------------------
extern "C" void kernel_launch(void* const* d_in, const int* in_sizes, int n_in,
                              void* d_out, int out_size)
{
    const float* query  = (const float*)d_in[0];
    const float* key    = (const float*)d_in[1];
    const int*   qidx   = (const int*)  d_in[2];
    const int*   kidx   = (const int*)  d_in[3];
    const float* paired = (const float*)d_in[4];
    const float* Wq     = (const float*)d_in[5];
    const float* Wkv    = (const float*)d_in[6];
    const float* Wb     = (const float*)d_in[7];
    const float* Wo     = (const float*)d_in[8];

    int n = in_sizes[0] / HC;   // 50000
    int m = in_sizes[2];        // 400000

    float* out_result = (float*)d_out;           // n*HC
    float* out_logit  = (float*)d_out + n * HC;  // m*NH

    cudaFuncSetAttribute(k_edge_mma, cudaFuncAttributeMaxDynamicSharedMemorySize,
                         SM_EDGE_TOTAL);

    int dev = 0, nsm = 148;
    cudaGetDevice(&dev);
    cudaDeviceGetAttribute(&nsm, cudaDevAttrMultiProcessorCount, dev);

    int ntiles = (m + TM - 1) / TM;
    int egrid  = ntiles < nsm ? ntiles : nsm;

    // Launch order keeps k_edge_mma in the profiled (4th) slot.
    k_init_max<<<(n * NH + 255) / 256, 256>>>(n);                        // 1
    k_proj<<<(n + 7) / 8, 128>>>(query, key, Wq, Wkv, n);                // 2
    k_init_agg<<<(n * HC + 255) / 256, 256>>>(n);                        // 3
    k_edge_mma<<<egrid, 512, SM_EDGE_TOTAL>>>(paired, Wb, qidx, kidx,    // 4
                                              out_logit, m);
    k_exp<<<(m * 2 + 255) / 256, 256>>>(qidx, out_logit, m);             // 5
    k_attn<<<(m * 2 + 255) / 256, 256>>>(qidx, m);                       // 6
    k_scatter<<<(m * 32 + 255) / 256, 256>>>(qidx, kidx, m);             // 7
    k_out<<<(n + 7) / 8, 128>>>(Wo, out_result, n);                      // 8
}

// round 6
// speedup vs baseline: 2.8247x; 1.0343x over previous
#include <cuda_runtime.h>
#include <cuda_bf16.h>
#include <math.h>
#include <stdint.h>

#define HC   128
#define NH   8
#define COLS 256
#define MAXN 50000
#define MAXM 400000
#define TM   128   // edges per tile

typedef unsigned long long ull;

// Scratch (device globals — no allocation allowed)
__device__ float g_q[MAXN * HC];
__device__ float g_k[MAXN * HC];
__device__ float g_v[MAXN * HC];
__device__ float g_agg[MAXN * HC];
__device__ float g_segmax[MAXN * NH];
__device__ float g_denom[MAXN * NH];
__device__ float g_ex[MAXM * NH];

__device__ __forceinline__ void atomicMaxFloat(float* addr, float val) {
    if (val >= 0.0f) atomicMax((int*)addr, __float_as_int(val));
    else             atomicMin((unsigned int*)addr, __float_as_uint(val));
}

__device__ __forceinline__ uint32_t smem_u32(const void* p) {
    uint32_t a;
    asm("{ .reg .u64 t; cvta.to.shared.u64 t, %1; cvt.u32.u64 %0, t; }"
        : "=r"(a) : "l"(p));
    return a;
}

// ---------------------------------------------------------------------------
// mma.sync / ldmatrix (base PTX ISA — valid for compute_103)
// ---------------------------------------------------------------------------
#define MMA_BF16(c, a, b) \
    asm volatile( \
        "mma.sync.aligned.m16n8k16.row.col.f32.bf16.bf16.f32 " \
        "{%0,%1,%2,%3}, {%4,%5,%6,%7}, {%8,%9}, {%0,%1,%2,%3};" \
        : "+f"((c)[0]), "+f"((c)[1]), "+f"((c)[2]), "+f"((c)[3]) \
        : "r"((a)[0]), "r"((a)[1]), "r"((a)[2]), "r"((a)[3]), \
          "r"((b)[0]), "r"((b)[1]))

#define LDSM_X4(r, addr) \
    asm volatile("ldmatrix.sync.aligned.m8n8.x4.shared.b16 {%0,%1,%2,%3}, [%4];" \
        : "=r"((r)[0]), "=r"((r)[1]), "=r"((r)[2]), "=r"((r)[3]) : "r"(addr))

// Row pitch 136 bf16 = 272 B (17x16B, conflict-free ldmatrix).
#define PITCHB  272

// hi/lo bf16 split of a float2, stored as packed bf16x2 words
__device__ __forceinline__ void split_store(char* hi_p, char* lo_p, float2 x) {
    __nv_bfloat162 hi2 = __floats2bfloat162_rn(x.x, x.y);
    float r0 = x.x - __bfloat162float(hi2.x);
    float r1 = x.y - __bfloat162float(hi2.y);
    __nv_bfloat162 lo2 = __floats2bfloat162_rn(r0, r1);
    *(uint32_t*)hi_p = *(uint32_t*)&hi2;
    *(uint32_t*)lo_p = *(uint32_t*)&lo2;
}

// ---------------- SMEM layouts ----------------
// edge kernel
#define SM_WB   0                       // [split 2][pass 2][nc 128][k 136] bf16
#define SM_WB_S 69632
#define SM_WB_P 34816
#define SM_A    139264                  // [split 2][row 128][k 136] bf16
#define SM_A_S  34816
#define SM_PART 208896                  // [wn 4][128][8] f32
#define SM_QI   225280
#define SM_KI   225792
#define SM_EDGE_TOTAL 226304
// proj / out kernels: A buf + W buf, each [split 2][128][136] bf16
#define PM_A    0
#define PM_S    34816                   // split stride
#define PM_W    69632
#define PM_TOTAL 139264

// ---------------------------------------------------------------------------
// Init kernels
// ---------------------------------------------------------------------------
__global__ void k_init_max(int n) {
    int i = blockIdx.x * blockDim.x + threadIdx.x;
    if (i < n * NH) ((unsigned int*)g_segmax)[i] = 0xFF800000u;  // -inf
}
__global__ void k_init_agg(int n) {
    int i = blockIdx.x * blockDim.x + threadIdx.x;
    if (i < n * HC) g_agg[i] = 0.0f;
    if (i < n * NH) g_denom[i] = 0.0f;
}

// ---------------------------------------------------------------------------
// Projection GEMMs via bf16 split-3 mma: g_q = query@Wq ; g_k,g_v = key@Wkv.
// Per tile (128 nodes): 3 chunks, each stages a 128x128 W block hi/lo and
// runs a 128x128x128 split-3 MMA, acc in fp32 regs, direct STG.
// ---------------------------------------------------------------------------
__global__ __launch_bounds__(512, 1) void k_proj_mma(
    const float* __restrict__ query, const float* __restrict__ key,
    const float* __restrict__ Wq, const float* __restrict__ Wkv, int n)
{
    extern __shared__ char smem[];
    uint32_t sbase = smem_u32(smem);

    int tid  = threadIdx.x;
    int warp = tid >> 5;
    int lane = tid & 31;
    int wm   = warp >> 2;
    int wn   = warp & 3;
    int g    = lane >> 2;
    int t4   = lane & 3;

    uint32_t aoff = (uint32_t)(((lane & 7) + 8 * ((lane >> 3) & 1)) * PITCHB
                               + ((lane >> 4) & 1) * 16);
    uint32_t boff = (uint32_t)(((lane & 7) + 8 * ((lane >> 4) & 1)) * PITCHB
                               + ((lane >> 3) & 1) * 16);
    uint32_t a_base = sbase + PM_A + (uint32_t)(wm * 32) * PITCHB + aoff;
    uint32_t b_base = sbase + PM_W + (uint32_t)(wn * 32) * PITCHB + boff;

    int ntiles = (n + TM - 1) / TM;
    for (int tile = blockIdx.x; tile < ntiles; tile += gridDim.x) {
        int nb = tile * TM;

#pragma unroll 1
        for (int chunk = 0; chunk < 3; chunk++) {
            __syncthreads();  // prior chunk readers done

            // stage A (query for chunk 0, key for chunk 1; chunk 2 reuses key)
            if (chunk < 2) {
                const float* Asrc = (chunk == 0) ? query : key;
                for (int i = tid; i < TM * 64; i += 512) {
                    int r = i >> 6, cp = i & 63;
                    int row = nb + r;
                    float2 x = (row < n) ? ((const float2*)Asrc)[(size_t)row * 64 + cp]
                                         : make_float2(0.f, 0.f);
                    size_t off = (size_t)r * PITCHB + (size_t)cp * 4;
                    split_store(smem + PM_A + off, smem + PM_A + PM_S + off, x);
                }
            }
            // stage W chunk: cols cb..cb+127 of Wsrc (ldW), transposed [nc][k]
            {
                const float* Wsrc = (chunk == 0) ? Wq : Wkv;
                int ldW = (chunk == 0) ? HC : COLS;
                int cb  = (chunk == 2) ? HC : 0;
                for (int i = tid; i < 128 * 64; i += 512) {
                    int nc = i >> 6, kp = i & 63;
                    float2 w = make_float2(Wsrc[(2 * kp)     * ldW + cb + nc],
                                           Wsrc[(2 * kp + 1) * ldW + cb + nc]);
                    size_t off = (size_t)nc * PITCHB + (size_t)kp * 4;
                    split_store(smem + PM_W + off, smem + PM_W + PM_S + off, w);
                }
            }
            __syncthreads();

            float acc[2][4][4];
#pragma unroll
            for (int mt = 0; mt < 2; mt++)
#pragma unroll
                for (int nt = 0; nt < 4; nt++)
#pragma unroll
                    for (int el = 0; el < 4; el++) acc[mt][nt][el] = 0.f;

#pragma unroll 2
            for (int ks = 0; ks < 8; ks++) {
                uint32_t bh[4][2], bl[4][2], ah[2][4], al[2][4];
                uint32_t bk = b_base + (uint32_t)ks * 32;
#pragma unroll
                for (int u2 = 0; u2 < 2; u2++) {
                    uint32_t tmp[4];
                    LDSM_X4(tmp, bk + (uint32_t)(u2 * 16) * PITCHB);
                    bh[2*u2][0] = tmp[0]; bh[2*u2][1] = tmp[1];
                    bh[2*u2+1][0] = tmp[2]; bh[2*u2+1][1] = tmp[3];
                    LDSM_X4(tmp, bk + PM_S + (uint32_t)(u2 * 16) * PITCHB);
                    bl[2*u2][0] = tmp[0]; bl[2*u2][1] = tmp[1];
                    bl[2*u2+1][0] = tmp[2]; bl[2*u2+1][1] = tmp[3];
                }
                uint32_t ak_ = a_base + (uint32_t)ks * 32;
#pragma unroll
                for (int mt = 0; mt < 2; mt++) {
                    LDSM_X4(ah[mt], ak_ + (uint32_t)(mt * 16) * PITCHB);
                    LDSM_X4(al[mt], ak_ + PM_S + (uint32_t)(mt * 16) * PITCHB);
                }
#pragma unroll
                for (int mt = 0; mt < 2; mt++)
#pragma unroll
                    for (int nt = 0; nt < 4; nt++) {
                        MMA_BF16(acc[mt][nt], ah[mt], bh[nt]);
                        MMA_BF16(acc[mt][nt], ah[mt], bl[nt]);
                        MMA_BF16(acc[mt][nt], al[mt], bh[nt]);
                    }
            }

            // write out
            float* outp = (chunk == 0) ? g_q : (chunk == 1) ? g_k : g_v;
#pragma unroll
            for (int mt = 0; mt < 2; mt++)
#pragma unroll
                for (int rh = 0; rh < 2; rh++) {
                    int row = nb + wm * 32 + mt * 16 + g + rh * 8;
                    if (row < n) {
#pragma unroll
                        for (int nt = 0; nt < 4; nt++) {
                            int col = wn * 32 + nt * 8 + t4 * 2;
                            *(float2*)&outp[(size_t)row * HC + col] =
                                make_float2(acc[mt][nt][rh*2], acc[mt][nt][rh*2+1]);
                        }
                    }
                }
        }
    }
}

// ---------------------------------------------------------------------------
// Edge kernel: bf16 split-3 mma.sync GEMM (PR @ Wb) fused with bias-modulated
// logits + segment max. (unchanged from R5 — validated)
// ---------------------------------------------------------------------------
__global__ __launch_bounds__(512, 1) void k_edge_mma(
    const float* __restrict__ paired, const float* __restrict__ Wb,
    const int* __restrict__ qidx, const int* __restrict__ kidx,
    float* __restrict__ out_logit, int m)
{
    extern __shared__ char smem[];
    uint32_t sbase = smem_u32(smem);

    int tid  = threadIdx.x;
    int warp = tid >> 5;
    int lane = tid & 31;
    int wm   = warp >> 2;
    int wn   = warp & 3;
    int g    = lane >> 2;
    int t4   = lane & 3;

    int*   s_qi   = (int*)(smem + SM_QI);
    int*   s_ki   = (int*)(smem + SM_KI);
    float* s_part = (float*)(smem + SM_PART);

    for (int i = tid; i < 2 * 128 * 64; i += 512) {
        int kp = i & 63;
        int nc = (i >> 6) & 127;
        int p  = i >> 13;
        int wn_ = nc >> 5, ln = nc & 31;
        int u = ln >> 4, bias = (ln >> 3) & 1, off = ln & 7;
        int ch   = p * 64 + wn_ * 16 + u * 8 + off;
        int wcol = bias * 128 + ch;
        float2 w = make_float2(Wb[(2 * kp)     * COLS + wcol],
                               Wb[(2 * kp + 1) * COLS + wcol]);
        size_t off_b = (size_t)p * SM_WB_P + (size_t)nc * PITCHB + (size_t)kp * 4;
        split_store(smem + SM_WB + off_b, smem + SM_WB + SM_WB_S + off_b, w);
    }

    uint32_t aoff = (uint32_t)(((lane & 7) + 8 * ((lane >> 3) & 1)) * PITCHB
                               + ((lane >> 4) & 1) * 16);
    uint32_t boff = (uint32_t)(((lane & 7) + 8 * ((lane >> 4) & 1)) * PITCHB
                               + ((lane >> 3) & 1) * 16);
    uint32_t a_base = sbase + SM_A  + (uint32_t)(wm * 32) * PITCHB + aoff;
    uint32_t b_base = sbase + SM_WB + (uint32_t)(wn * 32) * PITCHB + boff;

    int ntiles = (m + TM - 1) / TM;
    for (int tile = blockIdx.x; tile < ntiles; tile += gridDim.x) {
        int ebase = tile * TM;
        __syncthreads();

        for (int i = tid; i < TM * 64; i += 512) {
            int r = i >> 6, cp = i & 63;
            int e = ebase + r;
            float2 x = (e < m) ? ((const float2*)paired)[(size_t)e * 64 + cp]
                               : make_float2(0.f, 0.f);
            size_t off_a = (size_t)r * PITCHB + (size_t)cp * 4;
            split_store(smem + SM_A + off_a, smem + SM_A + SM_A_S + off_a, x);
        }
        if (tid < TM) {
            int e = ebase + tid;
            s_qi[tid] = (e < m) ? qidx[e] : 0;
            s_ki[tid] = (e < m) ? kidx[e] : 0;
        }
        __syncthreads();

        float part[4][2];
#pragma unroll
        for (int a = 0; a < 4; a++) { part[a][0] = 0.f; part[a][1] = 0.f; }

#pragma unroll
        for (int p = 0; p < 2; p++) {
            float acc[2][4][4];
#pragma unroll
            for (int mt = 0; mt < 2; mt++)
#pragma unroll
                for (int nt = 0; nt < 4; nt++)
#pragma unroll
                    for (int el = 0; el < 4; el++) acc[mt][nt][el] = 0.f;

#pragma unroll 2
            for (int ks = 0; ks < 8; ks++) {
                uint32_t bh[4][2], bl[4][2], ah[2][4], al[2][4];
                uint32_t bk = b_base + (uint32_t)p * SM_WB_P + (uint32_t)ks * 32;
#pragma unroll
                for (int u2 = 0; u2 < 2; u2++) {
                    uint32_t tmp[4];
                    LDSM_X4(tmp, bk + (uint32_t)(u2 * 16) * PITCHB);
                    bh[2*u2][0] = tmp[0]; bh[2*u2][1] = tmp[1];
                    bh[2*u2+1][0] = tmp[2]; bh[2*u2+1][1] = tmp[3];
                    LDSM_X4(tmp, bk + SM_WB_S + (uint32_t)(u2 * 16) * PITCHB);
                    bl[2*u2][0] = tmp[0]; bl[2*u2][1] = tmp[1];
                    bl[2*u2+1][0] = tmp[2]; bl[2*u2+1][1] = tmp[3];
                }
                uint32_t ak_ = a_base + (uint32_t)ks * 32;
#pragma unroll
                for (int mt = 0; mt < 2; mt++) {
                    LDSM_X4(ah[mt], ak_ + (uint32_t)(mt * 16) * PITCHB);
                    LDSM_X4(al[mt], ak_ + SM_A_S + (uint32_t)(mt * 16) * PITCHB);
                }
#pragma unroll
                for (int mt = 0; mt < 2; mt++)
#pragma unroll
                    for (int nt = 0; nt < 4; nt++) {
                        MMA_BF16(acc[mt][nt], ah[mt], bh[nt]);
                        MMA_BF16(acc[mt][nt], ah[mt], bl[nt]);
                        MMA_BF16(acc[mt][nt], al[mt], bh[nt]);
                    }
            }

#pragma unroll
            for (int mt = 0; mt < 2; mt++)
#pragma unroll
                for (int rh = 0; rh < 2; rh++) {
                    int eli = wm * 32 + mt * 16 + g + rh * 8;
                    const float* qrow = g_q + (size_t)s_qi[eli] * HC;
                    const float* krow = g_k + (size_t)s_ki[eli] * HC;
#pragma unroll
                    for (int u = 0; u < 2; u++) {
                        int c = p * 64 + wn * 16 + u * 8 + t4 * 2;
                        float2 q2 = *(const float2*)(qrow + c);
                        float2 k2 = *(const float2*)(krow + c);
                        float bm0 = acc[mt][2*u][rh*2],   bm1 = acc[mt][2*u][rh*2+1];
                        float ba0 = acc[mt][2*u+1][rh*2], ba1 = acc[mt][2*u+1][rh*2+1];
                        float qk0 = q2.x * k2.x;
                        float qk1 = q2.y * k2.y;
                        part[mt*2+rh][0] += fmaf(qk0, bm0, qk0) + q2.x * ba0;
                        part[mt*2+rh][1] += fmaf(qk1, bm1, qk1) + q2.y * ba1;
                    }
                }
        }

#pragma unroll
        for (int mt = 0; mt < 2; mt++)
#pragma unroll
            for (int rh = 0; rh < 2; rh++) {
                int eli = wm * 32 + mt * 16 + g + rh * 8;
                float2* sp = (float2*)&s_part[wn * 1024 + eli * 8 + t4 * 2];
                *sp = make_float2(part[mt*2+rh][0], part[mt*2+rh][1]);
            }
        __syncthreads();

#pragma unroll
        for (int j = 0; j < 2; j++) {
            int i  = tid + j * 512;
            int el = i >> 3, h = i & 7;
            int e  = ebase + el;
            if (e < m) {
                float lg = (s_part[i] + s_part[1024 + i])
                         + (s_part[2048 + i] + s_part[3072 + i]);
                out_logit[e * NH + h] = lg;
                atomicMaxFloat(&g_segmax[s_qi[el] * NH + h], lg);
            }
        }
    }
}

// ---------------------------------------------------------------------------
// exp + denom accumulation (float4 over 4 heads)
// ---------------------------------------------------------------------------
__global__ void k_exp(const int* __restrict__ qidx,
                      const float* __restrict__ logit, int m)
{
    int i = blockIdx.x * blockDim.x + threadIdx.x;
    if (i >= m * 2) return;
    int e = i >> 1, half = (i & 1) << 2;
    int qi = qidx[e];
    float4 lg = ((const float4*)logit)[i];
    float4 mx = *(const float4*)&g_segmax[qi * NH + half];
    float4 ex = make_float4(expf(lg.x - mx.x), expf(lg.y - mx.y),
                            expf(lg.z - mx.z), expf(lg.w - mx.w));
    ((float4*)g_ex)[i] = ex;
    atomicAdd((float4*)&g_denom[qi * NH + half], ex);
}

// ---------------------------------------------------------------------------
// scatter (normalization fused): agg[qi] += (ex/denom) * v[ki]
// ---------------------------------------------------------------------------
__global__ void k_scatter(const int* __restrict__ qidx,
                          const int* __restrict__ kidx, int m)
{
    int i = blockIdx.x * blockDim.x + threadIdx.x;
    if (i >= m * 32) return;
    int e  = i >> 5;
    int c4 = (i & 31) << 2;
    int qi = qidx[e];
    float4 v  = *(const float4*)&g_v[kidx[e] * HC + c4];
    float4 ex = *(const float4*)&g_ex[(e << 3) + (c4 & 7)];
    float4 dn = *(const float4*)&g_denom[qi * NH + (c4 & 7)];
    float4 val = make_float4((ex.x / dn.x) * v.x, (ex.y / dn.y) * v.y,
                             (ex.z / dn.z) * v.z, (ex.w / dn.w) * v.w);
    atomicAdd((float4*)&g_agg[qi * HC + c4], val);
}

// ---------------------------------------------------------------------------
// result = agg @ Wo via bf16 split-3 mma (same shape as one proj chunk)
// ---------------------------------------------------------------------------
__global__ __launch_bounds__(512, 1) void k_out_mma(
    const float* __restrict__ Wo, float* __restrict__ out, int n)
{
    extern __shared__ char smem[];
    uint32_t sbase = smem_u32(smem);

    int tid  = threadIdx.x;
    int warp = tid >> 5;
    int lane = tid & 31;
    int wm   = warp >> 2;
    int wn   = warp & 3;
    int g    = lane >> 2;
    int t4   = lane & 3;

    uint32_t aoff = (uint32_t)(((lane & 7) + 8 * ((lane >> 3) & 1)) * PITCHB
                               + ((lane >> 4) & 1) * 16);
    uint32_t boff = (uint32_t)(((lane & 7) + 8 * ((lane >> 4) & 1)) * PITCHB
                               + ((lane >> 3) & 1) * 16);
    uint32_t a_base = sbase + PM_A + (uint32_t)(wm * 32) * PITCHB + aoff;
    uint32_t b_base = sbase + PM_W + (uint32_t)(wn * 32) * PITCHB + boff;

    int ntiles = (n + TM - 1) / TM;
    for (int tile = blockIdx.x; tile < ntiles; tile += gridDim.x) {
        int nb = tile * TM;
        __syncthreads();

        for (int i = tid; i < TM * 64; i += 512) {
            int r = i >> 6, cp = i & 63;
            int row = nb + r;
            float2 x = (row < n) ? ((const float2*)g_agg)[(size_t)row * 64 + cp]
                                 : make_float2(0.f, 0.f);
            size_t off = (size_t)r * PITCHB + (size_t)cp * 4;
            split_store(smem + PM_A + off, smem + PM_A + PM_S + off, x);
        }
        for (int i = tid; i < 128 * 64; i += 512) {
            int nc = i >> 6, kp = i & 63;
            float2 w = make_float2(Wo[(2 * kp)     * HC + nc],
                                   Wo[(2 * kp + 1) * HC + nc]);
            size_t off = (size_t)nc * PITCHB + (size_t)kp * 4;
            split_store(smem + PM_W + off, smem + PM_W + PM_S + off, w);
        }
        __syncthreads();

        float acc[2][4][4];
#pragma unroll
        for (int mt = 0; mt < 2; mt++)
#pragma unroll
            for (int nt = 0; nt < 4; nt++)
#pragma unroll
                for (int el = 0; el < 4; el++) acc[mt][nt][el] = 0.f;

#pragma unroll 2
        for (int ks = 0; ks < 8; ks++) {
            uint32_t bh[4][2], bl[4][2], ah[2][4], al[2][4];
            uint32_t bk = b_base + (uint32_t)ks * 32;
#pragma unroll
            for (int u2 = 0; u2 < 2; u2++) {
                uint32_t tmp[4];
                LDSM_X4(tmp, bk + (uint32_t)(u2 * 16) * PITCHB);
                bh[2*u2][0] = tmp[0]; bh[2*u2][1] = tmp[1];
                bh[2*u2+1][0] = tmp[2]; bh[2*u2+1][1] = tmp[3];
                LDSM_X4(tmp, bk + PM_S + (uint32_t)(u2 * 16) * PITCHB);
                bl[2*u2][0] = tmp[0]; bl[2*u2][1] = tmp[1];
                bl[2*u2+1][0] = tmp[2]; bl[2*u2+1][1] = tmp[3];
            }
            uint32_t ak_ = a_base + (uint32_t)ks * 32;
#pragma unroll
            for (int mt = 0; mt < 2; mt++) {
                LDSM_X4(ah[mt], ak_ + (uint32_t)(mt * 16) * PITCHB);
                LDSM_X4(al[mt], ak_ + PM_S + (uint32_t)(mt * 16) * PITCHB);
            }
#pragma unroll
            for (int mt = 0; mt < 2; mt++)
#pragma unroll
                for (int nt = 0; nt < 4; nt++) {
                    MMA_BF16(acc[mt][nt], ah[mt], bh[nt]);
                    MMA_BF16(acc[mt][nt], ah[mt], bl[nt]);
                    MMA_BF16(acc[mt][nt], al[mt], bh[nt]);
                }
        }

#pragma unroll
        for (int mt = 0; mt < 2; mt++)
#pragma unroll
            for (int rh = 0; rh < 2; rh++) {
                int row = nb + wm * 32 + mt * 16 + g + rh * 8;
                if (row < n) {
#pragma unroll
                    for (int nt = 0; nt < 4; nt++) {
                        int col = wn * 32 + nt * 8 + t4 * 2;
                        *(float2*)&out[(size_t)row * HC + col] =
                            make_float2(acc[mt][nt][rh*2], acc[mt][nt][rh*2+1]);
                    }
                }
            }
    }
}

// ---------------------------------------------------------------------------
extern "C" void kernel_launch(void* const* d_in, const int* in_sizes, int n_in,
                              void* d_out, int out_size)
{
    const float* query  = (const float*)d_in[0];
    const float* key    = (const float*)d_in[1];
    const int*   qidx   = (const int*)  d_in[2];
    const int*   kidx   = (const int*)  d_in[3];
    const float* paired = (const float*)d_in[4];
    const float* Wq     = (const float*)d_in[5];
    const float* Wkv    = (const float*)d_in[6];
    const float* Wb     = (const float*)d_in[7];
    const float* Wo     = (const float*)d_in[8];

    int n = in_sizes[0] / HC;   // 50000
    int m = in_sizes[2];        // 400000

    float* out_result = (float*)d_out;           // n*HC
    float* out_logit  = (float*)d_out + n * HC;  // m*NH

    cudaFuncSetAttribute(k_edge_mma, cudaFuncAttributeMaxDynamicSharedMemorySize,
                         SM_EDGE_TOTAL);
    cudaFuncSetAttribute(k_proj_mma, cudaFuncAttributeMaxDynamicSharedMemorySize,
                         PM_TOTAL);
    cudaFuncSetAttribute(k_out_mma, cudaFuncAttributeMaxDynamicSharedMemorySize,
                         PM_TOTAL);

    int dev = 0, nsm = 148;
    cudaGetDevice(&dev);
    cudaDeviceGetAttribute(&nsm, cudaDevAttrMultiProcessorCount, dev);

    int etiles = (m + TM - 1) / TM;
    int egrid  = etiles < nsm ? etiles : nsm;
    int ptiles = (n + TM - 1) / TM;
    int pgrid  = ptiles < nsm ? ptiles : nsm;

    // Launch order keeps k_edge_mma in the profiled (4th) slot.
    k_init_max<<<(n * NH + 255) / 256, 256>>>(n);                        // 1
    k_proj_mma<<<pgrid, 512, PM_TOTAL>>>(query, key, Wq, Wkv, n);        // 2
    k_init_agg<<<(n * HC + 255) / 256, 256>>>(n);                        // 3
    k_edge_mma<<<egrid, 512, SM_EDGE_TOTAL>>>(paired, Wb, qidx, kidx,    // 4
                                              out_logit, m);
    k_exp<<<(m * 2 + 255) / 256, 256>>>(qidx, out_logit, m);             // 5
    k_scatter<<<(m * 32 + 255) / 256, 256>>>(qidx, kidx, m);             // 6
    k_out_mma<<<pgrid, 512, PM_TOTAL>>>(Wo, out_result, n);              // 7
}